// round 16
// baseline (speedup 1.0000x reference)
#include <cuda_runtime.h>
#include <cuda_fp16.h>
#include <math.h>
#include <stdint.h>

// ---------------- problem constants ----------------
#define BB    4096
#define NINP  1024
#define C0    2000
#define C1    10000
#define NH    2002
#define N0T   8000
#define N1T   22000
#define H0D   256
#define H1D   64

#define NHP   2048
#define N0P   8064
#define N1P   22016
#define GH    (NHP/128)    // 16
#define G0    (N0P/128)    // 63
#define G1    (N1P/128)    // 172

#define LOG2E 1.4426950408889634f
#define LN2   0.6931471805599453f

#define RS    72
#define TILE_B (128*RS*2)      // 18432
// hidden kernel (3 products)
#define OFF_AH 0
#define OFF_AL TILE_B
#define OFF_BH (2*TILE_B)
#define OFF_BL (3*TILE_B)
#define SMEM_HID (4*TILE_B)    // 73728
// LSE: 2 stages x (A tile + B tile)
#define STAGE_B (2*TILE_B)     // 36864
#define SMEM_LSE (2*STAGE_B)   // 73728

#define GD_BLKS 1536           // 512 x 3 (256-thread blocks)
#define LSE_PERIODS 172
#define LSE_BLKS (LSE_PERIODS*17)

// ---------------- device scratch ----------------
__device__ int   g_n0, g_n1;
__device__ int   g_idx0[BB], g_idx1[BB];
__device__ int   g_cid[BB], g_gind[BB], g_t0[BB], g_t1[BB];
__device__ __half g_Xhi[BB*NINP],  g_Xlo[BB*NINP];
__device__ __half g_Whh[NHP*NINP], g_Whl[NHP*NINP];
__device__ __half g_W10h[H0D*NINP], g_W10l[H0D*NINP];
__device__ __half g_W11h[128*NINP], g_W11l[128*NINP];
__device__ __half g_W20h[N0P*H0D], g_W20l[N0P*H0D];
__device__ __half g_W21h[N1P*H1D], g_W21l[N1P*H1D];
__device__ float g_H0[BB*H0D]; __device__ __half g_H0h[BB*H0D], g_H0l[BB*H0D];
__device__ float g_H1[BB*H1D]; __device__ __half g_H1h[BB*H1D], g_H1l[BB*H1D];
__device__ float g_zh[BB], g_z0[BB], g_z1[BB];   // base-2 units
// partial sums, 2 halves per 128-col group
__device__ float g_psH[(size_t)BB*GH*2];
__device__ float g_ps0[(size_t)BB*G0*2];
__device__ float g_ps1[(size_t)BB*G1*2];
__device__ float g_blocksum[16];

// ---------------- helpers ----------------
__device__ __forceinline__ uint32_t smem_u32(const void* p) {
    uint32_t a;
    asm("{ .reg .u64 t; cvta.to.shared.u64 t, %1; cvt.u32.u64 %0, t; }" : "=r"(a) : "l"(p));
    return a;
}
__device__ __forceinline__ void ldmx4(uint32_t* r, uint32_t addr) {
    asm volatile("ldmatrix.sync.aligned.m8n8.x4.shared.b16 {%0,%1,%2,%3}, [%4];"
        : "=r"(r[0]), "=r"(r[1]), "=r"(r[2]), "=r"(r[3]) : "r"(addr));
}
__device__ __forceinline__ void ldmx2(uint32_t* r, uint32_t addr) {
    asm volatile("ldmatrix.sync.aligned.m8n8.x2.shared.b16 {%0,%1}, [%2];"
        : "=r"(r[0]), "=r"(r[1]) : "r"(addr));
}
__device__ __forceinline__ void mma16816_f32(float* c, const uint32_t* a, const uint32_t* b) {
    asm volatile("mma.sync.aligned.m16n8k16.row.col.f32.f16.f16.f32 "
        "{%0,%1,%2,%3}, {%4,%5,%6,%7}, {%8,%9}, {%0,%1,%2,%3};"
        : "+f"(c[0]), "+f"(c[1]), "+f"(c[2]), "+f"(c[3])
        : "r"(a[0]), "r"(a[1]), "r"(a[2]), "r"(a[3]), "r"(b[0]), "r"(b[1]));
}
__device__ __forceinline__ void mma16816_f16(uint32_t* c, const uint32_t* a, const uint32_t* b) {
    asm volatile("mma.sync.aligned.m16n8k16.row.col.f16.f16.f16.f16 "
        "{%0,%1}, {%2,%3,%4,%5}, {%6,%7}, {%0,%1};"
        : "+r"(c[0]), "+r"(c[1])
        : "r"(a[0]), "r"(a[1]), "r"(a[2]), "r"(a[3]), "r"(b[0]), "r"(b[1]));
}
__device__ __forceinline__ uint32_t ex2u(uint32_t t) {
    asm("ex2.approx.f16x2 %0, %0;" : "+r"(t));
    return t;
}
__device__ __forceinline__ uint32_t hadd2u(uint32_t a, uint32_t b) {
    uint32_t d;
    asm("add.f16x2 %0, %1, %2;" : "=r"(d) : "r"(a), "r"(b));
    return d;
}
#define CP_ASYNC16(dst, src) \
    asm volatile("cp.async.cg.shared.global [%0], [%1], 16;" :: "r"(dst), "l"(src) : "memory")
#define CP_COMMIT() asm volatile("cp.async.commit_group;" ::: "memory")

// ---------------- init ----------------
__global__ void init_kernel() { g_n0 = 0; g_n1 = 0; }

// ---------------- fused prologue ----------------
__global__ void fusedprep_kernel(const float* __restrict__ X,
                                 const int* __restrict__ target,
                                 const float* __restrict__ Wh,
                                 const float* __restrict__ W10,
                                 const float* __restrict__ W20,
                                 const float* __restrict__ W11,
                                 const float* __restrict__ W21) {
    __shared__ float t[32][33];
    int tid = threadIdx.y * 32 + threadIdx.x;
    int z = blockIdx.x;

    if (z < 16) {                         // prep
        int i = z * 256 + tid;
        int tg = target[i];
        int cid = (tg >= C0) + (tg >= C1);
        g_cid[i]  = cid;
        g_gind[i] = (cid == 0) ? tg : (C0 + cid - 1);
        int a = tg - C0; a = a < 0 ? 0 : a; a = a > N0T-1 ? N0T-1 : a; g_t0[i] = a;
        int b = tg - C1; b = b < 0 ? 0 : b; b = b > N1T-1 ? N1T-1 : b; g_t1[i] = b;
        if (cid == 1)      g_idx0[atomicAdd(&g_n0, 1)] = i;
        else if (cid == 2) g_idx1[atomicAdd(&g_n1, 1)] = i;
        return;
    }
    z -= 16;
    if (z < BB*NINP/256) {                // splitx
        int i = z * 256 + tid;
        float v = X[i];
        __half h = __float2half(v);
        g_Xhi[i] = h;
        g_Xlo[i] = __float2half(v - __half2float(h));
        return;
    }
    z -= BB*NINP/256;

    const float* src; int R, C, Cpad, Cb; __half *dhi, *dlo; float scale;
    if (z < 2048)        { src=Wh;  R=NINP; C=NH;  Cpad=NHP; dhi=g_Whh;  dlo=g_Whl;  scale=LOG2E; Cb=64; }
    else if (z < 2304)   { z-=2048; src=W10; R=NINP; C=H0D; Cpad=H0D; dhi=g_W10h; dlo=g_W10l; scale=1.0f; Cb=8; }
    else if (z < 2432)   { z-=2304; src=W11; R=NINP; C=H1D; Cpad=128; dhi=g_W11h; dlo=g_W11l; scale=1.0f; Cb=4; }
    else if (z < 4448)   { z-=2432; src=W20; R=H0D;  C=N0T; Cpad=N0P; dhi=g_W20h; dlo=g_W20l; scale=LOG2E; Cb=252; }
    else                 { z-=4448; src=W21; R=H1D;  C=N1T; Cpad=N1P; dhi=g_W21h; dlo=g_W21l; scale=LOG2E; Cb=688; }
    int cb = (z % Cb) * 32, rb = (z / Cb) * 32;
#pragma unroll
    for (int e = 0; e < 4; e++) {
        int rr = rb + threadIdx.y + e*8, cc = cb + threadIdx.x;
        t[threadIdx.y + e*8][threadIdx.x] = (rr < R && cc < C) ? src[(size_t)rr*C + cc] : 0.f;
    }
    __syncthreads();
#pragma unroll
    for (int e = 0; e < 4; e++) {
        int n = cb + threadIdx.y + e*8, k = rb + threadIdx.x;
        if (n < Cpad && k < R) {
            float v = t[threadIdx.x][threadIdx.y + e*8] * scale;
            __half h = __float2half(v);
            dhi[(size_t)n*R + k] = h;
            dlo[(size_t)n*R + k] = __float2half(v - __half2float(h));
        }
    }
}
#define FUSEDPREP_BLKS (16 + BB*NINP/256 + 2048 + 256 + 128 + 2016 + 1376)

// ---------------- hidden projections: 3-product split-fp16 mma ----------------
__global__ __launch_bounds__(256, 2)
void hidden_kernel() {
    int sel = (blockIdx.y == 2) ? 1 : 0;
    int by  = (blockIdx.y == 2) ? 0 : blockIdx.y;
    const __half *Ahi = g_Xhi, *Alo = g_Xlo, *Bhi, *Blo;
    int Nvalid, ldH; float* Hout; __half *Hh, *Hl;
    if (sel == 0) { Bhi=g_W10h; Blo=g_W10l; Nvalid=H0D; Hout=g_H0; Hh=g_H0h; Hl=g_H0l; ldH=H0D; }
    else          { Bhi=g_W11h; Blo=g_W11l; Nvalid=H1D; Hout=g_H1; Hh=g_H1h; Hl=g_H1l; ldH=H1D; }
    const int K = NINP;
    int rbase = blockIdx.x * 128;

    extern __shared__ __align__(16) char sm[];
    uint32_t sbase = smem_u32(sm);
    int tid = threadIdx.x, wid = tid >> 5, lane = tid & 31;
    int wm = wid >> 2, wn = wid & 3;

    float acc[4][4][4];
#pragma unroll
    for (int mt = 0; mt < 4; mt++)
#pragma unroll
        for (int nt = 0; nt < 4; nt++)
#pragma unroll
            for (int c = 0; c < 4; c++) acc[mt][nt][c] = 0.f;

    uint32_t aoff = (uint32_t)(((wm*64 + (lane & 15)) * RS + (lane >> 4) * 8) * 2);
    uint32_t boff = (uint32_t)(((wn*32 + (lane & 7)) * RS + ((lane >> 3) & 1) * 8) * 2);
    uint32_t aAH = sbase + OFF_AH + aoff, aAL = sbase + OFF_AL + aoff;
    uint32_t aBH = sbase + OFF_BH + boff, aBL = sbase + OFF_BL + boff;

    for (int ch = 0; ch < K/64; ch++) {
        int k0 = ch << 6;
#pragma unroll
        for (int e = 0; e < 4; e++) {
            int f = e*256 + tid, row = f >> 3, u = f & 7;
            size_t go = (size_t)(rbase + row) * K + k0 + u*8;
            uint32_t so = (uint32_t)((row*RS + u*8) * 2);
            *(uint4*)(sm + OFF_AH + so) = *(const uint4*)(Ahi + go);
            *(uint4*)(sm + OFF_AL + so) = *(const uint4*)(Alo + go);
            size_t gb = (size_t)(by*128 + row) * K + k0 + u*8;
            *(uint4*)(sm + OFF_BH + so) = *(const uint4*)(Bhi + gb);
            *(uint4*)(sm + OFF_BL + so) = *(const uint4*)(Blo + gb);
        }
        __syncthreads();
#pragma unroll
        for (int ks = 0; ks < 4; ks++) {
            uint32_t ah[4][4], al[4][4];
#pragma unroll
            for (int mt = 0; mt < 4; mt++) {
                uint32_t d = (uint32_t)(mt*16*RS*2 + ks*32);
                ldmx4(ah[mt], aAH + d);
                ldmx4(al[mt], aAL + d);
            }
#pragma unroll
            for (int nt = 0; nt < 4; nt++) {
                uint32_t d = (uint32_t)(nt*8*RS*2 + ks*32);
                uint32_t bh[2], bl[2];
                ldmx2(bh, aBH + d);
                ldmx2(bl, aBL + d);
#pragma unroll
                for (int mt = 0; mt < 4; mt++) {
                    mma16816_f32(acc[mt][nt], ah[mt], bh);
                    mma16816_f32(acc[mt][nt], ah[mt], bl);
                    mma16816_f32(acc[mt][nt], al[mt], bh);
                }
            }
        }
        __syncthreads();
    }

    int q = lane >> 2, r4 = lane & 3;
#pragma unroll
    for (int mt = 0; mt < 4; mt++)
#pragma unroll
        for (int nt = 0; nt < 4; nt++)
#pragma unroll
            for (int c = 0; c < 4; c++) {
                int row = rbase + wm*64 + mt*16 + q + (c >> 1)*8;
                int col = by*128 + wn*32 + nt*8 + r4*2 + (c & 1);
                if (col < Nvalid) {
                    float v = acc[mt][nt][c];
                    Hout[(size_t)row*ldH + col] = v;
                    __half hh = __float2half(v);
                    Hh[(size_t)row*ldH + col] = hh;
                    Hl[(size_t)row*ldH + col] = __float2half(v - __half2float(hh));
                }
            }
}

// ---------------- fused LSE + gatherdot (256-thread CTAs) --------------------
// blocks [0, GD_BLKS): gatherdot. Then period-17 decode: 3 head / 6 tail0 / 8 tail1.
// 8 warps = 4(m) x 2(n), each m32 x n64; f16 accumulators; warp-local epilogue
// writes per-64-col-half partials at pS[row*2G + 2*cy + wn]. One sync per iter.
__global__ __launch_bounds__(256, 2)
void lse_fused_kernel(const float* __restrict__ X) {
    int zb = blockIdx.x;
    int tid = threadIdx.x, wid = tid >> 5, lane = tid & 31;

    if (zb < GD_BLKS) {
        int sel = zb / 512, bx = zb % 512;
        const float* A; const __half *Whi, *Wlo; const int* colidx; float* out; int K;
        if (sel == 0)      { A = X;    Whi = g_Whh;  Wlo = g_Whl;  colidx = g_gind; out = g_zh; K = NINP; }
        else if (sel == 1) { A = g_H0; Whi = g_W20h; Wlo = g_W20l; colidx = g_t0;   out = g_z0; K = H0D; }
        else               { A = g_H1; Whi = g_W21h; Wlo = g_W21l; colidx = g_t1;   out = g_z1; K = H1D; }
        int w = (bx * 256 + tid) >> 5;
        if (w >= BB) return;
        int c = colidx[w];
        float s = 0.f;
        for (int k = lane*2; k < K; k += 64) {
            float2 a = *(const float2*)&A[(size_t)w*K + k];
            float2 h = __half22float2(*(const __half2*)&Whi[(size_t)c*K + k]);
            float2 l = __half22float2(*(const __half2*)&Wlo[(size_t)c*K + k]);
            s += a.x * (h.x + l.x);
            s += a.y * (h.y + l.y);
        }
#pragma unroll
        for (int o = 16; o > 0; o >>= 1) s += __shfl_xor_sync(0xffffffffu, s, o);
        if (lane == 0) out[w] = s;
        return;
    }

    // -------- LSE decode --------
    int z = zb - GD_BLKS;
    int p = z / 17, i = z % 17;
    int sel, bx, by0;
    if (i < 3) {
        int idx = p*3 + i; if (idx >= 512) return;
        sel = 0; bx = idx & 31; by0 = idx >> 5;
    } else if (i < 9) {
        int idx = p*6 + (i - 3); if (idx >= 1024) return;
        sel = 1; bx = idx & 31; by0 = (idx >> 5) * 2;
    } else {
        int idx = p*8 + (i - 9); if (idx >= 1376) return;
        sel = 2; bx = idx & 31; by0 = (idx >> 5) * 4;
    }

    const __half *Ahi, *Bhi;
    int K, Nvalid, G, cnt, T;
    const int* rowlist;
    float* pS;
    if (sel == 0)      { Ahi=g_Xhi;  K=NINP; Bhi=g_Whh;  Nvalid=NH;  G=GH; pS=g_psH; rowlist=nullptr; cnt=BB;   T=1; }
    else if (sel == 1) { Ahi=g_H0h;  K=H0D;  Bhi=g_W20h; Nvalid=N0T; G=G0; pS=g_ps0; rowlist=g_idx0; cnt=g_n0; T=2; }
    else               { Ahi=g_H1h;  K=H1D;  Bhi=g_W21h; Nvalid=N1T; G=G1; pS=g_ps1; rowlist=g_idx1; cnt=g_n1; T=4; }

    int rbase = bx * 128;
    if (rbase >= cnt) return;

    extern __shared__ __align__(16) char sm[];
    uint32_t sbase = smem_u32(sm);
    int wm = wid >> 1, wn = wid & 1;   // 4m x 2n

    // f16 accumulators: 2 m-tiles x 8 n8-tiles x 2 regs
    uint32_t facc[2][8][2];
#pragma unroll
    for (int mt = 0; mt < 2; mt++)
#pragma unroll
        for (int nt = 0; nt < 8; nt++) { facc[mt][nt][0] = 0; facc[mt][nt][1] = 0; }

    // load slots: 4 x 16B per matrix per chunk; row(e) = e*32 + (tid>>3)
    int rlocal = tid >> 3;
    int u8 = (tid & 7) * 8;
    uint32_t so0 = (uint32_t)((rlocal*RS + u8) * 2);
    int lrowK[4];
#pragma unroll
    for (int e = 0; e < 4; e++) {
        int row = e*32 + rlocal;
        int grow = rbase + row; if (grow >= cnt) grow = cnt - 1;
        lrowK[e] = (rowlist ? rowlist[grow] : grow) * K;
    }

    int nch = K >> 6;
    int iters = nch * T;

    // prologue: iter 0 into stage 0
    {
        int cy0 = by0 < G ? by0 : G - 1;
        int bbase = cy0 * 128;
#pragma unroll
        for (int e = 0; e < 4; e++) {
            uint32_t so = so0 + (uint32_t)(e*32*RS*2);
            CP_ASYNC16(sbase + so,          Ahi + (size_t)lrowK[e] + u8);
            CP_ASYNC16(sbase + TILE_B + so, Bhi + (size_t)(bbase + e*32 + rlocal)*K + u8);
        }
        CP_COMMIT();
    }

    uint32_t aoff  = (uint32_t)(((wm*32 + (lane & 15)) * RS + (lane >> 4) * 8) * 2);
    uint32_t boff4 = (uint32_t)(((wn*64 + (lane & 7) + ((lane >> 4) << 3)) * RS + ((lane >> 3) & 1) * 8) * 2);

    int q = lane >> 2, r4 = lane & 3;
    int ch = 0, cyi = 0;

    for (int it = 0; it < iters; it++) {
        asm volatile("cp.async.wait_group 0;" ::: "memory");
        __syncthreads();
        if (it + 1 < iters) {
            int ch2 = ch + 1, cy2i = cyi;
            if (ch2 == nch) { ch2 = 0; cy2i++; }
            int cy2 = by0 + cy2i; if (cy2 > G - 1) cy2 = G - 1;
            int k0 = ch2 << 6;
            int bbase = cy2 * 128;
            uint32_t st = ((it + 1) & 1) * STAGE_B;
#pragma unroll
            for (int e = 0; e < 4; e++) {
                uint32_t so = so0 + (uint32_t)(e*32*RS*2);
                CP_ASYNC16(sbase + st + so,          Ahi + (size_t)lrowK[e] + k0 + u8);
                CP_ASYNC16(sbase + st + TILE_B + so, Bhi + (size_t)(bbase + e*32 + rlocal)*K + k0 + u8);
            }
            CP_COMMIT();
        }
        uint32_t sb = sbase + (it & 1) * STAGE_B;
        uint32_t aA = sb + aoff, aB4 = sb + TILE_B + boff4;
#pragma unroll
        for (int ks = 0; ks < 4; ks++) {
            uint32_t a4[2][4];
            ldmx4(a4[0], aA + (uint32_t)(ks*32));
            ldmx4(a4[1], aA + (uint32_t)(16*RS*2 + ks*32));
#pragma unroll
            for (int ntp = 0; ntp < 4; ntp++) {
                uint32_t bq[4];
                ldmx4(bq, aB4 + (uint32_t)(ntp*16*RS*2 + ks*32));
#pragma unroll
                for (int mt = 0; mt < 2; mt++) {
                    mma16816_f16(facc[mt][ntp*2 + 0], a4[mt], bq);
                    mma16816_f16(facc[mt][ntp*2 + 1], a4[mt], bq + 2);
                }
            }
        }

        // epilogue at last chunk of this col tile (warp-local, sync-free)
        if (ch == nch - 1) {
            int cy = by0 + cyi;
            if (cy < G) {
                bool edge = (cy == G - 1);
#pragma unroll
                for (int mt = 0; mt < 2; mt++) {
#pragma unroll
                    for (int h = 0; h < 2; h++) {
                        uint32_t e8[8];
#pragma unroll
                        for (int nt = 0; nt < 8; nt++) {
                            uint32_t t = facc[mt][nt][h];
                            if (edge) {
                                int col0 = cy*128 + wn*64 + nt*8 + r4*2;
                                if (col0 >= Nvalid) t = 0xFC00FC00u;   // -inf,-inf
                            }
                            e8[nt] = ex2u(t);
                        }
#pragma unroll
                        for (int j = 0; j < 4; j++) e8[j] = hadd2u(e8[j], e8[j + 4]);
                        e8[0] = hadd2u(e8[0], e8[1]);
                        e8[2] = hadd2u(e8[2], e8[3]);
                        float2 f0 = __half22float2(*(__half2*)&e8[0]);
                        float2 f1 = __half22float2(*(__half2*)&e8[2]);
                        float s = (f0.x + f0.y) + (f1.x + f1.y);
                        s += __shfl_xor_sync(0xffffffffu, s, 1);
                        s += __shfl_xor_sync(0xffffffffu, s, 2);
                        if (r4 == 0) {
                            int row = wm*32 + mt*16 + q + h*8;
                            int grow = rbase + row;
                            if (grow < cnt) {
                                int orow = rowlist ? rowlist[grow] : grow;
                                pS[(size_t)orow*G*2 + cy*2 + wn] = s;
                            }
                        }
                    }
                }
            }
#pragma unroll
            for (int mt = 0; mt < 2; mt++)
#pragma unroll
                for (int nt = 0; nt < 8; nt++) { facc[mt][nt][0] = 0; facc[mt][nt][1] = 0; }
            ch = 0; cyi++;
        } else {
            ch++;
        }
    }
}

// ---------------- combine + deterministic loss reduction ----------------
__global__ void combine_kernel(float* __restrict__ out) {
    __shared__ float red[256];
    int i = blockIdx.x * 256 + threadIdx.x;

    float s = 0.f;
    for (int g = 0; g < GH*2; g++) s += g_psH[(size_t)i*GH*2 + g];
    float o = g_zh[i] - log2f(s);

    int cid = g_cid[i];
    if (cid == 1) {
        float s2 = 0.f;
        for (int g = 0; g < G0*2; g++) s2 += g_ps0[(size_t)i*G0*2 + g];
        o += g_z0[i] - log2f(s2);
    } else if (cid == 2) {
        float s2 = 0.f;
        for (int g = 0; g < G1*2; g++) s2 += g_ps1[(size_t)i*G1*2 + g];
        o += g_z1[i] - log2f(s2);
    }
    o *= LN2;
    out[i] = o;

    red[threadIdx.x] = o;
    __syncthreads();
    for (int st = 128; st > 0; st >>= 1) {
        if (threadIdx.x < st) red[threadIdx.x] += red[threadIdx.x + st];
        __syncthreads();
    }
    if (threadIdx.x == 0) g_blocksum[blockIdx.x] = red[0];
}

__global__ void finalize_kernel(float* __restrict__ out, int out_size) {
    float s = 0.f;
    for (int i = 0; i < 16; i++) s += g_blocksum[i];
    if (out_size > BB) out[BB] = -s / (float)BB;
}

// ---------------- launch ----------------
extern "C" void kernel_launch(void* const* d_in, const int* in_sizes, int n_in,
                              void* d_out, int out_size) {
    const float* X    = (const float*)d_in[0];
    const int*   tgt  = (const int*)d_in[1];
    const float* Wh   = (const float*)d_in[2];
    const float* W1_0 = (const float*)d_in[3];
    const float* W2_0 = (const float*)d_in[4];
    const float* W1_1 = (const float*)d_in[5];
    const float* W2_1 = (const float*)d_in[6];
    float* out = (float*)d_out;

    cudaFuncSetAttribute(hidden_kernel,    cudaFuncAttributeMaxDynamicSharedMemorySize, SMEM_HID);
    cudaFuncSetAttribute(lse_fused_kernel, cudaFuncAttributeMaxDynamicSharedMemorySize, SMEM_LSE);

    init_kernel<<<1, 1>>>();
    fusedprep_kernel<<<FUSEDPREP_BLKS, dim3(32, 8)>>>(X, tgt, Wh, W1_0, W2_0, W1_1, W2_1);
    hidden_kernel<<<dim3(BB/128, 3), 256, SMEM_HID>>>();
    lse_fused_kernel<<<GD_BLKS + LSE_BLKS, 256, SMEM_LSE>>>(X);
    combine_kernel<<<BB/256, 256>>>(out);
    finalize_kernel<<<1, 1>>>(out, out_size);
}

// round 17
// speedup vs baseline: 1.2555x; 1.2555x over previous
#include <cuda_runtime.h>
#include <cuda_fp16.h>
#include <math.h>
#include <stdint.h>

// ---------------- problem constants ----------------
#define BB    4096
#define NINP  1024
#define C0    2000
#define C1    10000
#define NH    2002
#define N0T   8000
#define N1T   22000
#define H0D   256
#define H1D   64

#define NHP   2048
#define N0P   8064
#define N1P   22016
#define GH    (NHP/128)    // 16
#define G0    (N0P/128)    // 63
#define G1    (N1P/128)    // 172

#define LOG2E 1.4426950408889634f
#define LN2   0.6931471805599453f

#define RS    72
#define TILE_B (128*RS*2)      // 18432
// LSE: 2 stages x (A tile + B tile)
#define STAGE_B (2*TILE_B)     // 36864
#define SMEM_MIX (2*STAGE_B)   // 73728
// hidden sub-layout (within same dynamic smem)
#define HOFF_AH 0
#define HOFF_AL 9216
#define HOFF_BH 18432
#define HOFF_BL 36864          // total 55296 < 73728

// Launch A decode: [0,192) hidden | [192,1216) gd-head | [1216,1728) head LSE
#define LA_HID   192
#define LA_GDH   1024
#define LA_BLKS  (LA_HID + LA_GDH + 512)
// Launch B decode: [0,1024) gd-t0 | [1024,2048) gd-t1 | [2048, +2460) tails 5:7
#define LB_TAIL_PERIODS 205
#define LB_BLKS  (2048 + LB_TAIL_PERIODS*12)

// ---------------- device scratch ----------------
__device__ int   g_n0, g_n1;
__device__ int   g_idx0[BB], g_idx1[BB];
__device__ int   g_cid[BB], g_gind[BB], g_t0[BB], g_t1[BB];
__device__ __half g_Xhi[BB*NINP],  g_Xlo[BB*NINP];
__device__ __half g_Whh[NHP*NINP], g_Whl[NHP*NINP];
__device__ __half g_W10h[H0D*NINP], g_W10l[H0D*NINP];
__device__ __half g_W11h[128*NINP], g_W11l[128*NINP];
__device__ __half g_W20h[N0P*H0D], g_W20l[N0P*H0D];
__device__ __half g_W21h[N1P*H1D], g_W21l[N1P*H1D];
__device__ float g_H0[BB*H0D]; __device__ __half g_H0h[BB*H0D], g_H0l[BB*H0D];
__device__ float g_H1[BB*H1D]; __device__ __half g_H1h[BB*H1D], g_H1l[BB*H1D];
__device__ float g_zh[BB], g_z0[BB], g_z1[BB];   // base-2 units
__device__ float g_psH[(size_t)BB*GH];
__device__ float g_ps0[(size_t)BB*G0];
__device__ float g_ps1[(size_t)BB*G1];
__device__ float g_blocksum[16];

// ---------------- helpers ----------------
__device__ __forceinline__ uint32_t smem_u32(const void* p) {
    uint32_t a;
    asm("{ .reg .u64 t; cvta.to.shared.u64 t, %1; cvt.u32.u64 %0, t; }" : "=r"(a) : "l"(p));
    return a;
}
__device__ __forceinline__ void ldmx4(uint32_t* r, uint32_t addr) {
    asm volatile("ldmatrix.sync.aligned.m8n8.x4.shared.b16 {%0,%1,%2,%3}, [%4];"
        : "=r"(r[0]), "=r"(r[1]), "=r"(r[2]), "=r"(r[3]) : "r"(addr));
}
__device__ __forceinline__ void mma16816_f32(float* c, const uint32_t* a, const uint32_t* b) {
    asm volatile("mma.sync.aligned.m16n8k16.row.col.f32.f16.f16.f32 "
        "{%0,%1,%2,%3}, {%4,%5,%6,%7}, {%8,%9}, {%0,%1,%2,%3};"
        : "+f"(c[0]), "+f"(c[1]), "+f"(c[2]), "+f"(c[3])
        : "r"(a[0]), "r"(a[1]), "r"(a[2]), "r"(a[3]), "r"(b[0]), "r"(b[1]));
}
__device__ __forceinline__ void mma16816_f16(uint32_t* c, const uint32_t* a, const uint32_t* b) {
    asm volatile("mma.sync.aligned.m16n8k16.row.col.f16.f16.f16.f16 "
        "{%0,%1}, {%2,%3,%4,%5}, {%6,%7}, {%0,%1};"
        : "+r"(c[0]), "+r"(c[1])
        : "r"(a[0]), "r"(a[1]), "r"(a[2]), "r"(a[3]), "r"(b[0]), "r"(b[1]));
}
__device__ __forceinline__ uint32_t ex2u(uint32_t t) {
    asm("ex2.approx.f16x2 %0, %0;" : "+r"(t));
    return t;
}
__device__ __forceinline__ uint32_t hadd2u(uint32_t a, uint32_t b) {
    uint32_t d;
    asm("add.f16x2 %0, %1, %2;" : "=r"(d) : "r"(a), "r"(b));
    return d;
}
#define CP_ASYNC16(dst, src) \
    asm volatile("cp.async.cg.shared.global [%0], [%1], 16;" :: "r"(dst), "l"(src) : "memory")
#define CP_COMMIT() asm volatile("cp.async.commit_group;" ::: "memory")

// ---------------- init ----------------
__global__ void init_kernel() { g_n0 = 0; g_n1 = 0; }

// ---------------- fused prologue: prep + splitx + all tsplits ----------------
__global__ void fusedprep_kernel(const float* __restrict__ X,
                                 const int* __restrict__ target,
                                 const float* __restrict__ Wh,
                                 const float* __restrict__ W10,
                                 const float* __restrict__ W20,
                                 const float* __restrict__ W11,
                                 const float* __restrict__ W21) {
    __shared__ float t[32][33];
    int tid = threadIdx.y * 32 + threadIdx.x;
    int z = blockIdx.x;

    if (z < 16) {                         // prep
        int i = z * 256 + tid;
        int tg = target[i];
        int cid = (tg >= C0) + (tg >= C1);
        g_cid[i]  = cid;
        g_gind[i] = (cid == 0) ? tg : (C0 + cid - 1);
        int a = tg - C0; a = a < 0 ? 0 : a; a = a > N0T-1 ? N0T-1 : a; g_t0[i] = a;
        int b = tg - C1; b = b < 0 ? 0 : b; b = b > N1T-1 ? N1T-1 : b; g_t1[i] = b;
        if (cid == 1)      g_idx0[atomicAdd(&g_n0, 1)] = i;
        else if (cid == 2) g_idx1[atomicAdd(&g_n1, 1)] = i;
        return;
    }
    z -= 16;
    if (z < BB*NINP/256) {                // splitx
        int i = z * 256 + tid;
        float v = X[i];
        __half h = __float2half(v);
        g_Xhi[i] = h;
        g_Xlo[i] = __float2half(v - __half2float(h));
        return;
    }
    z -= BB*NINP/256;

    const float* src; int R, C, Cpad, Cb; __half *dhi, *dlo; float scale;
    if (z < 2048)        { src=Wh;  R=NINP; C=NH;  Cpad=NHP; dhi=g_Whh;  dlo=g_Whl;  scale=LOG2E; Cb=64; }
    else if (z < 2304)   { z-=2048; src=W10; R=NINP; C=H0D; Cpad=H0D; dhi=g_W10h; dlo=g_W10l; scale=1.0f; Cb=8; }
    else if (z < 2432)   { z-=2304; src=W11; R=NINP; C=H1D; Cpad=128; dhi=g_W11h; dlo=g_W11l; scale=1.0f; Cb=4; }
    else if (z < 4448)   { z-=2432; src=W20; R=H0D;  C=N0T; Cpad=N0P; dhi=g_W20h; dlo=g_W20l; scale=LOG2E; Cb=252; }
    else                 { z-=4448; src=W21; R=H1D;  C=N1T; Cpad=N1P; dhi=g_W21h; dlo=g_W21l; scale=LOG2E; Cb=688; }
    int cb = (z % Cb) * 32, rb = (z / Cb) * 32;
#pragma unroll
    for (int e = 0; e < 4; e++) {
        int rr = rb + threadIdx.y + e*8, cc = cb + threadIdx.x;
        t[threadIdx.y + e*8][threadIdx.x] = (rr < R && cc < C) ? src[(size_t)rr*C + cc] : 0.f;
    }
    __syncthreads();
#pragma unroll
    for (int e = 0; e < 4; e++) {
        int n = cb + threadIdx.y + e*8, k = rb + threadIdx.x;
        if (n < Cpad && k < R) {
            float v = t[threadIdx.x][threadIdx.y + e*8] * scale;
            __half h = __float2half(v);
            dhi[(size_t)n*R + k] = h;
            dlo[(size_t)n*R + k] = __float2half(v - __half2float(h));
        }
    }
}
#define FUSEDPREP_BLKS (16 + BB*NINP/256 + 2048 + 256 + 128 + 2016 + 1376)

// ---------------- gatherdot body (128-thread blocks, 4 rows/block) ----------
__device__ __forceinline__ void gatherdot_body(int sel, int bx, int tid,
                                               const float* __restrict__ X) {
    int lane = tid & 31;
    const float* A; const __half *Whi, *Wlo; const int* colidx; float* out; int K;
    if (sel == 0)      { A = X;    Whi = g_Whh;  Wlo = g_Whl;  colidx = g_gind; out = g_zh; K = NINP; }
    else if (sel == 1) { A = g_H0; Whi = g_W20h; Wlo = g_W20l; colidx = g_t0;   out = g_z0; K = H0D; }
    else               { A = g_H1; Whi = g_W21h; Wlo = g_W21l; colidx = g_t1;   out = g_z1; K = H1D; }
    int w = (bx * 128 + tid) >> 5;
    if (w >= BB) return;
    int c = colidx[w];
    float s = 0.f;
    for (int k = lane*2; k < K; k += 64) {
        float2 a = *(const float2*)&A[(size_t)w*K + k];
        float2 h = __half22float2(*(const __half2*)&Whi[(size_t)c*K + k]);
        float2 l = __half22float2(*(const __half2*)&Wlo[(size_t)c*K + k]);
        s += a.x * (h.x + l.x);
        s += a.y * (h.y + l.y);
    }
#pragma unroll
    for (int o = 16; o > 0; o >>= 1) s += __shfl_xor_sync(0xffffffffu, s, o);
    if (lane == 0) out[w] = s;
}

// ---------------- LSE body (R15 config: 4 warps, m32n128, f16 acc) ----------
__device__ __forceinline__ void lse_body(int sel, int bx, int by0, int tid,
                                         char* sm, uint32_t sbase) {
    int wid = tid >> 5, lane = tid & 31;
    const __half *Ahi, *Bhi;
    int K, Nvalid, G, cnt, T;
    const int* rowlist;
    float* pS;
    if (sel == 0)      { Ahi=g_Xhi;  K=NINP; Bhi=g_Whh;  Nvalid=NH;  G=GH; pS=g_psH; rowlist=nullptr; cnt=BB;   T=1; }
    else if (sel == 1) { Ahi=g_H0h;  K=H0D;  Bhi=g_W20h; Nvalid=N0T; G=G0; pS=g_ps0; rowlist=g_idx0; cnt=g_n0; T=2; }
    else               { Ahi=g_H1h;  K=H1D;  Bhi=g_W21h; Nvalid=N1T; G=G1; pS=g_ps1; rowlist=g_idx1; cnt=g_n1; T=4; }

    int rbase = bx * 128;
    if (rbase >= cnt) return;

    uint32_t facc[2][16][2];
#pragma unroll
    for (int mt = 0; mt < 2; mt++)
#pragma unroll
        for (int nt = 0; nt < 16; nt++) { facc[mt][nt][0] = 0; facc[mt][nt][1] = 0; }

    int rlocal = tid >> 3;
    int u8 = (tid & 7) * 8;
    uint32_t so0 = (uint32_t)((rlocal*RS + u8) * 2);
    int lrowK[8];
#pragma unroll
    for (int e = 0; e < 8; e++) {
        int row = e*16 + rlocal;
        int grow = rbase + row; if (grow >= cnt) grow = cnt - 1;
        lrowK[e] = (rowlist ? rowlist[grow] : grow) * K;
    }

    int nch = K >> 6;
    int iters = nch * T;

    {
        int cy0 = by0 < G ? by0 : G - 1;
        int bbase = cy0 * 128;
#pragma unroll
        for (int e = 0; e < 8; e++) {
            uint32_t so = so0 + (uint32_t)(e*16*RS*2);
            CP_ASYNC16(sbase + so,          Ahi + (size_t)lrowK[e] + u8);
            CP_ASYNC16(sbase + TILE_B + so, Bhi + (size_t)(bbase + e*16 + rlocal)*K + u8);
        }
        CP_COMMIT();
    }

    uint32_t aoff  = (uint32_t)(((wid*32 + (lane & 15)) * RS + (lane >> 4) * 8) * 2);
    uint32_t boff4 = (uint32_t)((((lane & 7) + ((lane >> 4) << 3)) * RS + ((lane >> 3) & 1) * 8) * 2);

    int q = lane >> 2, r4 = lane & 3;
    int ch = 0, cyi = 0;

    for (int it = 0; it < iters; it++) {
        asm volatile("cp.async.wait_group 0;" ::: "memory");
        __syncthreads();
        if (it + 1 < iters) {
            int ch2 = ch + 1, cy2i = cyi;
            if (ch2 == nch) { ch2 = 0; cy2i++; }
            int cy2 = by0 + cy2i; if (cy2 > G - 1) cy2 = G - 1;
            int k0 = ch2 << 6;
            int bbase = cy2 * 128;
            uint32_t st = ((it + 1) & 1) * STAGE_B;
#pragma unroll
            for (int e = 0; e < 8; e++) {
                uint32_t so = so0 + (uint32_t)(e*16*RS*2);
                CP_ASYNC16(sbase + st + so,          Ahi + (size_t)lrowK[e] + k0 + u8);
                CP_ASYNC16(sbase + st + TILE_B + so, Bhi + (size_t)(bbase + e*16 + rlocal)*K + k0 + u8);
            }
            CP_COMMIT();
        }
        uint32_t sb = sbase + (it & 1) * STAGE_B;
        uint32_t aA = sb + aoff, aB4 = sb + TILE_B + boff4;
#pragma unroll
        for (int ks = 0; ks < 4; ks++) {
            uint32_t a4[2][4];
            ldmx4(a4[0], aA + (uint32_t)(ks*32));
            ldmx4(a4[1], aA + (uint32_t)(16*RS*2 + ks*32));
#pragma unroll
            for (int ntp = 0; ntp < 8; ntp++) {
                uint32_t bq[4];
                ldmx4(bq, aB4 + (uint32_t)(ntp*16*RS*2 + ks*32));
#pragma unroll
                for (int mt = 0; mt < 2; mt++) {
                    mma16816_f16(facc[mt][ntp*2 + 0], a4[mt], bq);
                    mma16816_f16(facc[mt][ntp*2 + 1], a4[mt], bq + 2);
                }
            }
        }

        if (ch == nch - 1) {
            int cy = by0 + cyi;
            if (cy < G) {
                bool edge = (cy == G - 1);
#pragma unroll
                for (int mt = 0; mt < 2; mt++) {
#pragma unroll
                    for (int h = 0; h < 2; h++) {
                        uint32_t e16[16];
#pragma unroll
                        for (int nt = 0; nt < 16; nt++) {
                            uint32_t t = facc[mt][nt][h];
                            if (edge) {
                                int col0 = cy*128 + nt*8 + r4*2;
                                if (col0 >= Nvalid) t = 0xFC00FC00u;
                            }
                            e16[nt] = ex2u(t);
                        }
#pragma unroll
                        for (int j = 0; j < 8; j++) e16[j] = hadd2u(e16[j], e16[j + 8]);
#pragma unroll
                        for (int j = 0; j < 4; j++) e16[j] = hadd2u(e16[j], e16[j + 4]);
                        float s = 0.f;
#pragma unroll
                        for (int j = 0; j < 4; j++) {
                            float2 f2 = __half22float2(*(__half2*)&e16[j]);
                            s += f2.x + f2.y;
                        }
                        s += __shfl_xor_sync(0xffffffffu, s, 1);
                        s += __shfl_xor_sync(0xffffffffu, s, 2);
                        if (r4 == 0) {
                            int row = wid*32 + mt*16 + q + h*8;
                            int grow = rbase + row;
                            if (grow < cnt) {
                                int orow = rowlist ? rowlist[grow] : grow;
                                pS[(size_t)orow*G + cy] = s;
                            }
                        }
                    }
                }
            }
#pragma unroll
            for (int mt = 0; mt < 2; mt++)
#pragma unroll
                for (int nt = 0; nt < 16; nt++) { facc[mt][nt][0] = 0; facc[mt][nt][1] = 0; }
            ch = 0; cyi++;
        } else {
            ch++;
        }
    }
}

// ---------------- hidden body (128 threads, 64 rows x 128 cols, 3-product) ---
__device__ __forceinline__ void hidden_body(int hsel, int bx, int by, int tid,
                                            char* sm, uint32_t sbase) {
    int wid = tid >> 5, lane = tid & 31;
    const __half *Ahi = g_Xhi, *Alo = g_Xlo, *Bhi, *Blo;
    int Nvalid, ldH; float* Hout; __half *Hh, *Hl;
    if (hsel == 0) { Bhi=g_W10h; Blo=g_W10l; Nvalid=H0D; Hout=g_H0; Hh=g_H0h; Hl=g_H0l; ldH=H0D; }
    else           { Bhi=g_W11h; Blo=g_W11l; Nvalid=H1D; Hout=g_H1; Hh=g_H1h; Hl=g_H1l; ldH=H1D; }
    const int K = NINP;
    int rbase = bx * 64;

    float acc[16][4];
#pragma unroll
    for (int nt = 0; nt < 16; nt++)
#pragma unroll
        for (int c = 0; c < 4; c++) acc[nt][c] = 0.f;

    uint32_t aoff = (uint32_t)(((wid*16 + (lane & 15)) * RS + (lane >> 4) * 8) * 2);
    uint32_t boff4 = (uint32_t)((((lane & 7) + ((lane >> 4) << 3)) * RS + ((lane >> 3) & 1) * 8) * 2);
    uint32_t aAH = sbase + HOFF_AH + aoff, aAL = sbase + HOFF_AL + aoff;
    uint32_t aBH = sbase + HOFF_BH + boff4, aBL = sbase + HOFF_BL + boff4;

    for (int chk = 0; chk < K/64; chk++) {
        int k0 = chk << 6;
        // A: 64 rows x 64k hi/lo
#pragma unroll
        for (int e = 0; e < 4; e++) {
            int f = e*128 + tid, row = f >> 3, u = f & 7;
            size_t go = (size_t)(rbase + row) * K + k0 + u*8;
            uint32_t so = (uint32_t)((row*RS + u*8) * 2);
            *(uint4*)(sm + HOFF_AH + so) = *(const uint4*)(Ahi + go);
            *(uint4*)(sm + HOFF_AL + so) = *(const uint4*)(Alo + go);
        }
        // B: 128 rows x 64k hi/lo
#pragma unroll
        for (int e = 0; e < 8; e++) {
            int f = e*128 + tid, row = f >> 3, u = f & 7;
            size_t gb = (size_t)(by*128 + row) * K + k0 + u*8;
            uint32_t so = (uint32_t)((row*RS + u*8) * 2);
            *(uint4*)(sm + HOFF_BH + so) = *(const uint4*)(Bhi + gb);
            *(uint4*)(sm + HOFF_BL + so) = *(const uint4*)(Blo + gb);
        }
        __syncthreads();
#pragma unroll
        for (int ks = 0; ks < 4; ks++) {
            uint32_t ah[4], al[4];
            ldmx4(ah, aAH + (uint32_t)(ks*32));
            ldmx4(al, aAL + (uint32_t)(ks*32));
#pragma unroll
            for (int ntp = 0; ntp < 8; ntp++) {
                uint32_t d = (uint32_t)(ntp*16*RS*2 + ks*32);
                uint32_t bh4[4], bl4[4];
                ldmx4(bh4, aBH + d);
                ldmx4(bl4, aBL + d);
                mma16816_f32(acc[ntp*2 + 0], ah, bh4);
                mma16816_f32(acc[ntp*2 + 0], ah, bl4);
                mma16816_f32(acc[ntp*2 + 0], al, bh4);
                mma16816_f32(acc[ntp*2 + 1], ah, bh4 + 2);
                mma16816_f32(acc[ntp*2 + 1], ah, bl4 + 2);
                mma16816_f32(acc[ntp*2 + 1], al, bh4 + 2);
            }
        }
        __syncthreads();
    }

    int q = lane >> 2, r4 = lane & 3;
#pragma unroll
    for (int nt = 0; nt < 16; nt++)
#pragma unroll
        for (int c = 0; c < 4; c++) {
            int row = rbase + wid*16 + q + (c >> 1)*8;
            int col = by*128 + nt*8 + r4*2 + (c & 1);
            if (col < Nvalid) {
                float v = acc[nt][c];
                Hout[(size_t)row*ldH + col] = v;
                __half hh = __float2half(v);
                Hh[(size_t)row*ldH + col] = hh;
                Hl[(size_t)row*ldH + col] = __float2half(v - __half2float(hh));
            }
        }
}

// ---------------- mixed launch A: hidden + gd-head + head LSE ----------------
__global__ __launch_bounds__(128, 3)
void mixA_kernel(const float* __restrict__ X) {
    extern __shared__ __align__(16) char sm[];
    uint32_t sbase = smem_u32(sm);
    int tid = threadIdx.x;
    int zb = blockIdx.x;
    if (zb < LA_HID) {
        int hsel, bx, by;
        if (zb < 128) { hsel = 0; bx = zb >> 1; by = zb & 1; }
        else          { hsel = 1; bx = zb - 128; by = 0; }
        hidden_body(hsel, bx, by, tid, sm, sbase);
        return;
    }
    zb -= LA_HID;
    if (zb < LA_GDH) { gatherdot_body(0, zb, tid, X); return; }
    zb -= LA_GDH;
    lse_body(0, zb & 31, zb >> 5, tid, sm, sbase);
}

// ---------------- mixed launch B: gd-tails + tail LSE ------------------------
__global__ __launch_bounds__(128, 3)
void mixB_kernel(const float* __restrict__ X) {
    extern __shared__ __align__(16) char sm[];
    uint32_t sbase = smem_u32(sm);
    int tid = threadIdx.x;
    int zb = blockIdx.x;
    if (zb < 1024) { gatherdot_body(1, zb, tid, X); return; }
    if (zb < 2048) { gatherdot_body(2, zb - 1024, tid, X); return; }
    int z = zb - 2048;
    int pp = z / 12, s = z % 12;
    if (s < 5) {
        int idx = pp*5 + s; if (idx >= 1024) return;
        lse_body(1, idx & 31, (idx >> 5) * 2, tid, sm, sbase);
    } else {
        int idx = pp*7 + (s - 5); if (idx >= 1376) return;
        lse_body(2, idx & 31, (idx >> 5) * 4, tid, sm, sbase);
    }
}

// ---------------- combine + deterministic loss reduction ----------------
__global__ void combine_kernel(float* __restrict__ out) {
    __shared__ float red[256];
    int i = blockIdx.x * 256 + threadIdx.x;

    float s = 0.f;
    for (int g = 0; g < GH; g++) s += g_psH[(size_t)i*GH + g];
    float o = g_zh[i] - log2f(s);

    int cid = g_cid[i];
    if (cid == 1) {
        float s2 = 0.f;
        for (int g = 0; g < G0; g++) s2 += g_ps0[(size_t)i*G0 + g];
        o += g_z0[i] - log2f(s2);
    } else if (cid == 2) {
        float s2 = 0.f;
        for (int g = 0; g < G1; g++) s2 += g_ps1[(size_t)i*G1 + g];
        o += g_z1[i] - log2f(s2);
    }
    o *= LN2;
    out[i] = o;

    red[threadIdx.x] = o;
    __syncthreads();
    for (int st = 128; st > 0; st >>= 1) {
        if (threadIdx.x < st) red[threadIdx.x] += red[threadIdx.x + st];
        __syncthreads();
    }
    if (threadIdx.x == 0) g_blocksum[blockIdx.x] = red[0];
}

__global__ void finalize_kernel(float* __restrict__ out, int out_size) {
    float s = 0.f;
    for (int i = 0; i < 16; i++) s += g_blocksum[i];
    if (out_size > BB) out[BB] = -s / (float)BB;
}

// ---------------- launch ----------------
extern "C" void kernel_launch(void* const* d_in, const int* in_sizes, int n_in,
                              void* d_out, int out_size) {
    const float* X    = (const float*)d_in[0];
    const int*   tgt  = (const int*)d_in[1];
    const float* Wh   = (const float*)d_in[2];
    const float* W1_0 = (const float*)d_in[3];
    const float* W2_0 = (const float*)d_in[4];
    const float* W1_1 = (const float*)d_in[5];
    const float* W2_1 = (const float*)d_in[6];
    float* out = (float*)d_out;

    cudaFuncSetAttribute(mixA_kernel, cudaFuncAttributeMaxDynamicSharedMemorySize, SMEM_MIX);
    cudaFuncSetAttribute(mixB_kernel, cudaFuncAttributeMaxDynamicSharedMemorySize, SMEM_MIX);

    init_kernel<<<1, 1>>>();
    fusedprep_kernel<<<FUSEDPREP_BLKS, dim3(32, 8)>>>(X, tgt, Wh, W1_0, W2_0, W1_1, W2_1);
    mixA_kernel<<<LA_BLKS, 128, SMEM_MIX>>>(X);
    mixB_kernel<<<LB_BLKS, 128, SMEM_MIX>>>(X);
    combine_kernel<<<BB/256, 256>>>(out);
    finalize_kernel<<<1, 1>>>(out, out_size);
}